// round 10
// baseline (speedup 1.0000x reference)
#include <cuda_runtime.h>
#include <cuda_bf16.h>
#include <cstdint>

// pass1: cp.async.bulk (TMA path) stages x into smem, 2-deep pipeline,
//        warps reduce rows from smem; segment sums + parallel ticket finalize.
// pass2: proven write-streaming kernel from the prebuilt table (~22.5us).

#define NROWS 131072
#define DIN   256
#define NSUB  64
#define RPB   128           // rows per block
#define BT    256           // 8 warps
#define GRID  (NROWS / RPB) // 1024
#define STAGE_ROWS  16
#define STAGE_BYTES (STAGE_ROWS * DIN * 4)   // 16384
#define NSTAGES     (RPB / STAGE_ROWS)       // 8

__device__ float g_rowsum[NROWS];
__device__ float g_segsum[NSUB];
__device__ float g_segcnt[NSUB];
__device__ float g_stab[NSUB];
__device__ int   g_ticket;

__device__ __forceinline__ uint32_t s2u(const void* p) {
    uint32_t a;
    asm("{ .reg .u64 t; cvta.to.shared.u64 t, %1; cvt.u32.u64 %0, t; }" : "=r"(a) : "l"(p));
    return a;
}
#define MBAR_INIT(a, c) asm volatile("mbarrier.init.shared.b64 [%0], %1;" :: "r"(a), "r"(c) : "memory")
#define MBAR_EXPECT_TX(a, b) asm volatile("mbarrier.arrive.expect_tx.shared.b64 _, [%0], %1;" :: "r"(a), "r"(b) : "memory")
#define MBAR_ARRIVE(a) asm volatile("mbarrier.arrive.shared.b64 _, [%0];" :: "r"(a) : "memory")
#define FENCE_ASYNC() asm volatile("fence.proxy.async.shared::cta;" ::: "memory")
#define BULK_G2S(dst, src, bytes, mbar) \
    asm volatile("cp.async.bulk.shared::cta.global.mbarrier::complete_tx::bytes [%0], [%1], %2, [%3];" \
                 :: "r"(dst), "l"(src), "r"(bytes), "r"(mbar) : "memory")

__device__ __forceinline__ void mbar_wait(uint32_t mbar, uint32_t parity) {
    uint32_t done;
    asm volatile("{\n\t.reg .pred p;\n\t"
                 "mbarrier.try_wait.parity.acquire.cta.shared::cta.b64 p, [%1], %2;\n\t"
                 "selp.b32 %0, 1, 0, p;\n\t}"
                 : "=r"(done) : "r"(mbar), "r"(parity) : "memory");
    if (!done) {
        asm volatile("{\n\t.reg .pred P1;\n\t"
                     "WL_%=:\n\t"
                     "mbarrier.try_wait.parity.acquire.cta.shared::cta.b64 P1, [%0], %1, 0x989680;\n\t"
                     "@P1 bra.uni WD_%=;\n\t"
                     "bra.uni WL_%=;\n\t"
                     "WD_%=:\n\t}"
                     :: "r"(mbar), "r"(parity) : "memory");
    }
}

__global__ __launch_bounds__(BT) void pass1_kernel(
    const float* __restrict__ x, const int* __restrict__ sub,
    const float* __restrict__ Gamma)
{
    __shared__ alignas(16) float4 buf[2][STAGE_ROWS * (DIN / 4)];  // 2 x 16KB
    __shared__ alignas(8) unsigned long long mbar[4];              // full0, full1, empty0, empty1
    __shared__ float ssum[NSUB];
    __shared__ float scnt[NSUB];
    __shared__ int   is_last;

    const int t = threadIdx.x, warp = t >> 5, lane = t & 31;
    const int rowbase = blockIdx.x * RPB;

    const uint32_t full0  = s2u(&mbar[0]), full1  = s2u(&mbar[1]);
    const uint32_t empty0 = s2u(&mbar[2]), empty1 = s2u(&mbar[3]);
    const uint32_t bufu[2] = { s2u(&buf[0][0]), s2u(&buf[1][0]) };

    if (t < NSUB) { ssum[t] = 0.f; scnt[t] = 0.f; }
    if (t == 0) {
        MBAR_INIT(full0, 1);  MBAR_INIT(full1, 1);
        MBAR_INIT(empty0, 8); MBAR_INIT(empty1, 8);
        FENCE_ASYNC();
    }
    __syncthreads();

    const char* gsrc = (const char*)(x + (size_t)rowbase * DIN);

    if (t == 0) {   // prologue: issue stages 0 and 1
        MBAR_EXPECT_TX(full0, STAGE_BYTES);
        BULK_G2S(bufu[0], gsrc, STAGE_BYTES, full0);
        MBAR_EXPECT_TX(full1, STAGE_BYTES);
        BULK_G2S(bufu[1], gsrc + STAGE_BYTES, STAGE_BYTES, full1);
    }

    #pragma unroll 1
    for (int s = 0; s < NSTAGES; s++) {
        const int slot = s & 1;
        const uint32_t phase = (uint32_t)((s >> 1) & 1);
        mbar_wait(slot ? full1 : full0, phase);

        // warp w reduces rows {w*2, w*2+1} of this stage
        const float4* p0 = &buf[slot][(warp * 2 + 0) * (DIN / 4)];
        const float4* p1 = &buf[slot][(warp * 2 + 1) * (DIN / 4)];
        float4 a0 = p0[lane], b0 = p0[lane + 32];
        float4 a1 = p1[lane], b1 = p1[lane + 32];
        float s0 = (a0.x + a0.y) + (a0.z + a0.w) + (b0.x + b0.y) + (b0.z + b0.w);
        float s1 = (a1.x + a1.y) + (a1.z + a1.w) + (b1.x + b1.y) + (b1.z + b1.w);
        #pragma unroll
        for (int o = 16; o; o >>= 1) {
            s0 += __shfl_xor_sync(0xffffffffu, s0, o);
            s1 += __shfl_xor_sync(0xffffffffu, s1, o);
        }
        if (lane < 2) {
            const float sv = lane ? s1 : s0;
            const int row = rowbase + s * STAGE_ROWS + warp * 2 + lane;
            g_rowsum[row] = sv;
            const int sg = __ldg(sub + row);
            atomicAdd(&ssum[sg], sv);
            atomicAdd(&scnt[sg], 1.f);
        }
        __syncwarp();
        if (lane == 0) MBAR_ARRIVE(slot ? empty1 : empty0);

        if (t == 0 && s < NSTAGES - 2) {    // issue stage s+2 once slot is drained
            mbar_wait(slot ? empty1 : empty0, phase);
            const uint32_t f = slot ? full1 : full0;
            MBAR_EXPECT_TX(f, STAGE_BYTES);
            BULK_G2S(bufu[slot], gsrc + (size_t)(s + 2) * STAGE_BYTES, STAGE_BYTES, f);
        }
    }
    __syncthreads();

    if (t < NSUB && scnt[t] != 0.f) {
        atomicAdd(&g_segsum[t], ssum[t]);
        atomicAdd(&g_segcnt[t], scnt[t]);
    }
    __syncthreads();

    if (t == 0) {
        __threadfence();
        is_last = (atomicAdd(&g_ticket, 1) == GRID - 1) ? 1 : 0;
    }
    __syncthreads();

    if (is_last) {   // parallel finalize: 64 threads, one segment each
        if (t < NSUB) {
            const float cnt = g_segcnt[t];
            const float m   = (cnt > 0.f) ? (g_segsum[t] / cnt) : g_rowsum[0];
            const float sv  = Gamma[0] * m;
            g_stab[t] = (sv > 0.f) ? 128.f * sv : 0.f;
            g_segsum[t] = 0.f;
            g_segcnt[t] = 0.f;
        }
        __syncthreads();
        if (t == 0) { g_ticket = 0; __threadfence(); }
    }
}

__global__ __launch_bounds__(BT) void pass2_kernel(
    const int*   __restrict__ sub,
    const float* __restrict__ Lambda,
    float*       __restrict__ out)
{
    __shared__ float stab[NSUB];
    const int t = threadIdx.x, warp = t >> 5, lane = t & 31;
    if (t < NSUB) stab[t] = g_stab[t];
    __syncthreads();

    const float lam = Lambda[0];
    const int rowbase = blockIdx.x * RPB + warp * 16;
    float4* obase = reinterpret_cast<float4*>(out) + (size_t)rowbase * (DIN / 4) + lane;

    #pragma unroll
    for (int j = 0; j < 16; j++) {
        const int row = rowbase + j;
        float o = lam * (g_rowsum[row] + stab[__ldg(sub + row)]);
        o = (o > 0.f) ? o : 0.f;
        const float4 v = make_float4(o, o, o, o);
        float4* p = obase + (size_t)j * 64;
        __stcs(p, v);
        __stcs(p + 32, v);
    }
}

extern "C" void kernel_launch(void* const* d_in, const int* in_sizes, int n_in,
                              void* d_out, int out_size)
{
    const float* x      = (const float*)d_in[0];
    const int*   sub    = (const int*)d_in[1];
    const float* Gamma  = (const float*)d_in[2];
    const float* Lambda = (const float*)d_in[3];
    float* out = (float*)d_out;

    pass1_kernel<<<GRID, BT>>>(x, sub, Gamma);
    pass2_kernel<<<GRID, BT>>>(sub, Lambda, out);
}

// round 11
// speedup vs baseline: 1.0314x; 1.0314x over previous
#include <cuda_runtime.h>
#include <cuda_bf16.h>
#include <cstdint>

// pass1: warp-specialized TMA pipeline. Warp 4 = dedicated producer issuing
//        cp.async.bulk stages (ring of 3 x 8KB); warps 0-3 reduce rows from
//        smem. Segment sums + parallel ticket finalize (proven R9).
// pass2: proven write-streaming kernel from prebuilt table (22.5us).

#define NROWS 131072
#define DIN   256
#define NSUB  64
#define RPB   128            // rows per block
#define BT    160            // warps 0-3 consumers, warp 4 producer
#define GRID  (NROWS / RPB)  // 1024
#define STAGE_ROWS  8
#define STAGE_BYTES (STAGE_ROWS * DIN * 4)   // 8192
#define NSTAGES     (RPB / STAGE_ROWS)       // 16
#define RING        3

__device__ float g_rowsum[NROWS];
__device__ float g_segsum[NSUB];
__device__ float g_segcnt[NSUB];
__device__ float g_stab[NSUB];
__device__ int   g_ticket;

__device__ __forceinline__ uint32_t s2u(const void* p) {
    uint32_t a;
    asm("{ .reg .u64 t; cvta.to.shared.u64 t, %1; cvt.u32.u64 %0, t; }" : "=r"(a) : "l"(p));
    return a;
}
#define MBAR_INIT(a, c) asm volatile("mbarrier.init.shared.b64 [%0], %1;" :: "r"(a), "r"(c) : "memory")
#define MBAR_EXPECT_TX(a, b) asm volatile("mbarrier.arrive.expect_tx.shared.b64 _, [%0], %1;" :: "r"(a), "r"(b) : "memory")
#define MBAR_ARRIVE(a) asm volatile("mbarrier.arrive.shared.b64 _, [%0];" :: "r"(a) : "memory")
#define FENCE_ASYNC() asm volatile("fence.proxy.async.shared::cta;" ::: "memory")
#define BULK_G2S(dst, src, bytes, mbar) \
    asm volatile("cp.async.bulk.shared::cta.global.mbarrier::complete_tx::bytes [%0], [%1], %2, [%3];" \
                 :: "r"(dst), "l"(src), "r"(bytes), "r"(mbar) : "memory")

__device__ __forceinline__ void mbar_wait(uint32_t mbar, uint32_t parity) {
    uint32_t done;
    asm volatile("{\n\t.reg .pred p;\n\t"
                 "mbarrier.try_wait.parity.acquire.cta.shared::cta.b64 p, [%1], %2;\n\t"
                 "selp.b32 %0, 1, 0, p;\n\t}"
                 : "=r"(done) : "r"(mbar), "r"(parity) : "memory");
    if (!done) {
        asm volatile("{\n\t.reg .pred P1;\n\t"
                     "WL_%=:\n\t"
                     "mbarrier.try_wait.parity.acquire.cta.shared::cta.b64 P1, [%0], %1, 0x989680;\n\t"
                     "@P1 bra.uni WD_%=;\n\t"
                     "bra.uni WL_%=;\n\t"
                     "WD_%=:\n\t}"
                     :: "r"(mbar), "r"(parity) : "memory");
    }
}

__global__ __launch_bounds__(BT) void pass1_kernel(
    const float* __restrict__ x, const int* __restrict__ sub,
    const float* __restrict__ Gamma)
{
    __shared__ alignas(128) float4 buf[RING][STAGE_ROWS * (DIN / 4)];  // 3 x 8KB
    __shared__ alignas(8) unsigned long long mb_full[RING];
    __shared__ alignas(8) unsigned long long mb_empty[RING];
    __shared__ float ssum[NSUB];
    __shared__ float scnt[NSUB];
    __shared__ int   is_last;

    const int t = threadIdx.x, warp = t >> 5, lane = t & 31;
    const int rowbase = blockIdx.x * RPB;

    uint32_t fullu[RING], emptyu[RING], bufu[RING];
    #pragma unroll
    for (int i = 0; i < RING; i++) {
        fullu[i]  = s2u(&mb_full[i]);
        emptyu[i] = s2u(&mb_empty[i]);
        bufu[i]   = s2u(&buf[i][0]);
    }

    if (t < NSUB) { ssum[t] = 0.f; scnt[t] = 0.f; }
    if (t == 0) {
        #pragma unroll
        for (int i = 0; i < RING; i++) {
            MBAR_INIT(fullu[i], 1);    // producer's expect_tx arrival + tx bytes
            MBAR_INIT(emptyu[i], 4);   // 4 consumer warps
        }
        FENCE_ASYNC();
    }
    __syncthreads();

    const char* gsrc = (const char*)(x + (size_t)rowbase * DIN);

    if (warp == 4) {
        // ---- dedicated producer ----
        if (lane == 0) {
            #pragma unroll 1
            for (int i = 0; i < NSTAGES; i++) {
                const int slot = i % RING;
                const uint32_t k = (uint32_t)(i / RING);
                mbar_wait(emptyu[slot], (k & 1u) ^ 1u);   // fresh barrier passes at k=0
                MBAR_EXPECT_TX(fullu[slot], STAGE_BYTES);
                BULK_G2S(bufu[slot], gsrc + (size_t)i * STAGE_BYTES, STAGE_BYTES, fullu[slot]);
            }
        }
    } else {
        // ---- consumers: warp w reduces rows {2w, 2w+1} of each stage ----
        #pragma unroll 1
        for (int i = 0; i < NSTAGES; i++) {
            const int slot = i % RING;
            const uint32_t k = (uint32_t)(i / RING);
            mbar_wait(fullu[slot], k & 1u);

            const float4* p0 = &buf[slot][(warp * 2 + 0) * (DIN / 4)];
            const float4* p1 = &buf[slot][(warp * 2 + 1) * (DIN / 4)];
            float4 a0 = p0[lane], b0 = p0[lane + 32];
            float4 a1 = p1[lane], b1 = p1[lane + 32];
            float s0 = (a0.x + a0.y) + (a0.z + a0.w) + (b0.x + b0.y) + (b0.z + b0.w);
            float s1 = (a1.x + a1.y) + (a1.z + a1.w) + (b1.x + b1.y) + (b1.z + b1.w);
            #pragma unroll
            for (int o = 16; o; o >>= 1) {
                s0 += __shfl_xor_sync(0xffffffffu, s0, o);
                s1 += __shfl_xor_sync(0xffffffffu, s1, o);
            }
            if (lane < 2) {
                const float sv = lane ? s1 : s0;
                const int row = rowbase + i * STAGE_ROWS + warp * 2 + lane;
                g_rowsum[row] = sv;
                const int sg = __ldg(sub + row);
                atomicAdd(&ssum[sg], sv);
                atomicAdd(&scnt[sg], 1.f);
            }
            __syncwarp();
            if (lane == 0) MBAR_ARRIVE(emptyu[slot]);
        }
    }
    __syncthreads();

    if (t < NSUB && scnt[t] != 0.f) {
        atomicAdd(&g_segsum[t], ssum[t]);
        atomicAdd(&g_segcnt[t], scnt[t]);
    }
    __syncthreads();

    if (t == 0) {
        __threadfence();
        is_last = (atomicAdd(&g_ticket, 1) == GRID - 1) ? 1 : 0;
    }
    __syncthreads();

    if (is_last) {   // parallel finalize: 64 threads, one segment each
        if (t < NSUB) {
            const float cnt = g_segcnt[t];
            const float m   = (cnt > 0.f) ? (g_segsum[t] / cnt) : g_rowsum[0];
            const float sv  = Gamma[0] * m;
            g_stab[t] = (sv > 0.f) ? 128.f * sv : 0.f;
            g_segsum[t] = 0.f;
            g_segcnt[t] = 0.f;
        }
        __syncthreads();
        if (t == 0) { g_ticket = 0; __threadfence(); }
    }
}

#define BT2 256
__global__ __launch_bounds__(BT2) void pass2_kernel(
    const int*   __restrict__ sub,
    const float* __restrict__ Lambda,
    float*       __restrict__ out)
{
    __shared__ float stab[NSUB];
    const int t = threadIdx.x, warp = t >> 5, lane = t & 31;
    if (t < NSUB) stab[t] = g_stab[t];
    __syncthreads();

    const float lam = Lambda[0];
    const int rowbase = blockIdx.x * RPB + warp * 16;
    float4* obase = reinterpret_cast<float4*>(out) + (size_t)rowbase * (DIN / 4) + lane;

    #pragma unroll
    for (int j = 0; j < 16; j++) {
        const int row = rowbase + j;
        float o = lam * (g_rowsum[row] + stab[__ldg(sub + row)]);
        o = (o > 0.f) ? o : 0.f;
        const float4 v = make_float4(o, o, o, o);
        float4* p = obase + (size_t)j * 64;
        __stcs(p, v);
        __stcs(p + 32, v);
    }
}

extern "C" void kernel_launch(void* const* d_in, const int* in_sizes, int n_in,
                              void* d_out, int out_size)
{
    const float* x      = (const float*)d_in[0];
    const int*   sub    = (const int*)d_in[1];
    const float* Gamma  = (const float*)d_in[2];
    const float* Lambda = (const float*)d_in[3];
    float* out = (float*)d_out;

    pass1_kernel<<<GRID, BT>>>(x, sub, Gamma);
    pass2_kernel<<<GRID, BT2>>>(sub, Lambda, out);
}